// round 2
// baseline (speedup 1.0000x reference)
#include <cuda_runtime.h>

// Problem constants (fixed for this problem instance)
#define N_NODES 4096
#define IN_CH   5
#define OUT_CH  2
#define EDGES   131072
#define KE      (IN_CH * EDGES)            // 655360 total edges
#define EI_N    (IN_CH * 2 * EDGES)        // 1310720 index elements

#define NN_ELEMS  (16777216)               // 4096*4096
#define H_ELEMS   (2 * 16777216)           // 33554432

// ---------------- device scratch (no allocation allowed) ----------------
__device__ int   g_is64;
__device__ int   g_ei[EI_N];                 // converted int32 edge indices
__device__ float g_w1s[OUT_CH * IN_CH];      // softmax(w1)
__device__ float g_w2s[OUT_CH * IN_CH];      // softmax(w2)
__device__ float g_A2[2][NN_ELEMS];          // dense A2 per channel (128 MB)
__device__ int   g_rowcnt[N_NODES + 1];
__device__ int   g_rowptr[N_NODES + 1];
__device__ int   g_rowfill[N_NODES];
__device__ int   g_cols[KE];
__device__ float g_v0[KE];                   // A1 values, channel 0 (CSR order)
__device__ float g_v1[KE];                   // A1 values, channel 1 (CSR order)

// ---------------- kernels ----------------

// Detect int64 vs int32 edge_index. Indices are < 4096, so if the buffer is
// little-endian int64, every odd 32-bit word is zero. For int32 random data
// the probability that 256 consecutive odd words are all zero is ~0.
__global__ void k_detect(const int* __restrict__ p) {
    int allzero = 1;
    for (int j = 0; j < 256; ++j)
        if (p[2 * j + 1] != 0) allzero = 0;
    g_is64 = allzero;
}

__global__ void k_convert(const void* __restrict__ ei) {
    int i = blockIdx.x * blockDim.x + threadIdx.x;
    if (i >= EI_N) return;
    int v;
    if (g_is64) v = (int)((const long long*)ei)[i];
    else        v = ((const int*)ei)[i];
    g_ei[i] = v;
}

// softmax over K for both weight matrices; writes W1, W2 to output tail only
// if the output buffer provably has room for them.
__global__ void k_softmax(const float* __restrict__ w1,
                          const float* __restrict__ w2,
                          float* __restrict__ out, int out_size) {
    if (threadIdx.x != 0 || blockIdx.x != 0) return;
    const int write_tail = (out_size >= H_ELEMS + 2 * OUT_CH * IN_CH);
    for (int o = 0; o < OUT_CH; ++o) {
        float m = -1e30f;
        for (int k = 0; k < IN_CH; ++k) m = fmaxf(m, w1[o * IN_CH + k]);
        float e[IN_CH], s = 0.f;
        for (int k = 0; k < IN_CH; ++k) { e[k] = expf(w1[o * IN_CH + k] - m); s += e[k]; }
        for (int k = 0; k < IN_CH; ++k) {
            float ws = e[k] / s;
            g_w1s[o * IN_CH + k] = ws;
            if (write_tail) out[H_ELEMS + o * IN_CH + k] = ws;
        }
    }
    for (int o = 0; o < OUT_CH; ++o) {
        float m = -1e30f;
        for (int k = 0; k < IN_CH; ++k) m = fmaxf(m, w2[o * IN_CH + k]);
        float e[IN_CH], s = 0.f;
        for (int k = 0; k < IN_CH; ++k) { e[k] = expf(w2[o * IN_CH + k] - m); s += e[k]; }
        for (int k = 0; k < IN_CH; ++k) {
            float ws = e[k] / s;
            g_w2s[o * IN_CH + k] = ws;
            if (write_tail) out[H_ELEMS + OUT_CH * IN_CH + o * IN_CH + k] = ws;
        }
    }
}

// Zero A2 scratch and row counters (must happen every launch — graph replay).
__global__ void k_zero() {
    size_t i = (size_t)blockIdx.x * blockDim.x + threadIdx.x;
    const size_t n4 = (size_t)H_ELEMS / 4;  // 8388608 float4s
    float4 z = make_float4(0.f, 0.f, 0.f, 0.f);
    float4* p = (float4*)&g_A2[0][0];
    for (size_t j = i; j < n4; j += (size_t)gridDim.x * blockDim.x) p[j] = z;
    if (i <= N_NODES) g_rowcnt[i] = 0;
}

// Pass A: scatter-add dense A2 for both channels + histogram rows for CSR.
__global__ void k_scatterA(const float* __restrict__ ev) {
    int i = blockIdx.x * blockDim.x + threadIdx.x;
    if (i >= KE) return;
    int k = i >> 17;           // i / EDGES
    int e = i & (EDGES - 1);   // i % EDGES
    int r = g_ei[(k * 2) * EDGES + e];
    int c = g_ei[(k * 2 + 1) * EDGES + e];
    float v = ev[i];           // edge_value is [K, E] -> flat index == i
    size_t off = (size_t)r * N_NODES + c;
    atomicAdd(&g_A2[0][off], g_w2s[0 * IN_CH + k] * v);
    atomicAdd(&g_A2[1][off], g_w2s[1 * IN_CH + k] * v);
    atomicAdd(&g_rowcnt[r], 1);
}

// Exclusive prefix sum over 4096 row counts (single block).
__global__ void k_prefix() {
    __shared__ int ssum[1024];
    int t = threadIdx.x;
    int c0 = g_rowcnt[t * 4 + 0];
    int c1 = g_rowcnt[t * 4 + 1];
    int c2 = g_rowcnt[t * 4 + 2];
    int c3 = g_rowcnt[t * 4 + 3];
    ssum[t] = c0 + c1 + c2 + c3;
    __syncthreads();
    if (t == 0) {
        int acc = 0;
        for (int j = 0; j < 1024; ++j) { int x = ssum[j]; ssum[j] = acc; acc += x; }
    }
    __syncthreads();
    int base = ssum[t];
    int p0 = base, p1 = base + c0, p2 = p1 + c1, p3 = p2 + c2;
    g_rowptr[t * 4 + 0] = p0;  g_rowfill[t * 4 + 0] = p0;
    g_rowptr[t * 4 + 1] = p1;  g_rowfill[t * 4 + 1] = p1;
    g_rowptr[t * 4 + 2] = p2;  g_rowfill[t * 4 + 2] = p2;
    g_rowptr[t * 4 + 3] = p3;  g_rowfill[t * 4 + 3] = p3;
    if (t == 1023) g_rowptr[4096] = p3 + c3;
}

// Pass B: fill CSR columns + per-channel A1 values.
__global__ void k_scatterB(const float* __restrict__ ev) {
    int i = blockIdx.x * blockDim.x + threadIdx.x;
    if (i >= KE) return;
    int k = i >> 17;
    int e = i & (EDGES - 1);
    int r = g_ei[(k * 2) * EDGES + e];
    int c = g_ei[(k * 2 + 1) * EDGES + e];
    float v = ev[i];
    int pos = atomicAdd(&g_rowfill[r], 1);
    g_cols[pos] = c;
    g_v0[pos] = g_w1s[0 * IN_CH + k] * v;
    g_v1[pos] = g_w1s[1 * IN_CH + k] * v;
}

// SpMM: one block per (channel, row). H[ch,row,:] = sum_j v_j * A2[ch, c_j, :].
// 256 threads, each owns 4 float4 column slices (16 columns). Edge (col, val)
// pairs are staged in shared and broadcast. Blocks are channel-major so each
// channel's 64 MB A2 working set fits in L2 during its wave.
__global__ void __launch_bounds__(256) k_spmm(float* __restrict__ out) {
    const int bx  = blockIdx.x;
    const int ch  = bx >> 12;
    const int row = bx & (N_NODES - 1);
    const int tid = threadIdx.x;

    const float4* __restrict__ A2c = (const float4*)&g_A2[ch][0];
    const float*  __restrict__ val = ch ? g_v1 : g_v0;

    const int start = g_rowptr[row];
    const int end   = g_rowptr[row + 1];

    __shared__ int   s_col[256];
    __shared__ float s_val[256];

    float4 a0 = make_float4(0.f, 0.f, 0.f, 0.f);
    float4 a1 = a0, a2 = a0, a3 = a0;

    for (int base = start; base < end; base += 256) {
        int n = min(256, end - base);
        if (tid < n) {
            s_col[tid] = g_cols[base + tid];
            s_val[tid] = val[base + tid];
        }
        __syncthreads();
        #pragma unroll 4
        for (int j = 0; j < n; ++j) {
            int   c = s_col[j];
            float v = s_val[j];
            const float4* r4 = A2c + (size_t)c * 1024 + tid;
            float4 b0 = r4[0];
            float4 b1 = r4[256];
            float4 b2 = r4[512];
            float4 b3 = r4[768];
            a0.x = fmaf(v, b0.x, a0.x); a0.y = fmaf(v, b0.y, a0.y);
            a0.z = fmaf(v, b0.z, a0.z); a0.w = fmaf(v, b0.w, a0.w);
            a1.x = fmaf(v, b1.x, a1.x); a1.y = fmaf(v, b1.y, a1.y);
            a1.z = fmaf(v, b1.z, a1.z); a1.w = fmaf(v, b1.w, a1.w);
            a2.x = fmaf(v, b2.x, a2.x); a2.y = fmaf(v, b2.y, a2.y);
            a2.z = fmaf(v, b2.z, a2.z); a2.w = fmaf(v, b2.w, a2.w);
            a3.x = fmaf(v, b3.x, a3.x); a3.y = fmaf(v, b3.y, a3.y);
            a3.z = fmaf(v, b3.z, a3.z); a3.w = fmaf(v, b3.w, a3.w);
        }
        __syncthreads();
    }

    float4* H4 = (float4*)(out + ((size_t)ch * N_NODES + row) * N_NODES);
    __stcs(H4 + tid        , a0);   // streaming stores: don't pollute L2
    __stcs(H4 + tid + 256  , a1);
    __stcs(H4 + tid + 512  , a2);
    __stcs(H4 + tid + 768  , a3);
}

// ---------------- launch ----------------
extern "C" void kernel_launch(void* const* d_in, const int* in_sizes, int n_in,
                              void* d_out, int out_size) {
    (void)in_sizes; (void)n_in;
    const void*  ei = d_in[0];                 // edge_index [5,2,E] int32 or int64
    const float* ev = (const float*)d_in[1];   // edge_value [5,E] fp32
    const float* w1 = (const float*)d_in[2];   // [2,5]
    const float* w2 = (const float*)d_in[3];   // [2,5]
    float* out = (float*)d_out;                // H [2,4096,4096] (++ W1 ++ W2)

    k_detect<<<1, 1>>>((const int*)ei);
    k_convert<<<(EI_N + 511) / 512, 512>>>(ei);
    k_softmax<<<1, 32>>>(w1, w2, out, out_size);
    k_zero<<<16384, 512>>>();
    k_scatterA<<<(KE + 511) / 512, 512>>>(ev);
    k_prefix<<<1, 1024>>>();
    k_scatterB<<<(KE + 511) / 512, 512>>>(ev);
    k_spmm<<<2 * N_NODES, 256>>>(out);
}

// round 3
// speedup vs baseline: 1.7931x; 1.7931x over previous
#include <cuda_runtime.h>
#include <cuda_fp16.h>

// Problem constants (fixed for this problem instance)
#define N_NODES 4096
#define IN_CH   5
#define OUT_CH  2
#define EDGES   131072
#define KE      (IN_CH * EDGES)            // 655360 total edges

#define NN_ELEMS  (16777216)               // 4096*4096
#define H_ELEMS   (2 * 16777216)           // 33554432
#define A2_SCALE  1024.0f
#define A2_DESCALE (1.0f / 1024.0f)

// ---------------- device scratch (no allocation allowed) ----------------
__device__ int     g_is64;
__device__ float   g_w1s[OUT_CH * IN_CH];    // softmax(w1)
__device__ float   g_w2s[OUT_CH * IN_CH];    // softmax(w2)
__device__ __half2 g_A2h[NN_ELEMS];          // A2, both channels interleaved, x1024 (64 MB)
__device__ int     g_rowcnt[N_NODES + 1];
__device__ int     g_rowptr[N_NODES + 1];
__device__ int     g_rowfill[N_NODES];
__device__ int     g_cols[KE];               // CSR cols of A1
__device__ float2  g_v01[KE];                // A1 values (ch0, ch1), CSR order

// ---------------- kernels ----------------

// Init: dtype detection + softmax of both weights + output tail (W1, W2).
// Indices are < 4096, so if the buffer is little-endian int64, every odd
// 32-bit word is zero; for int32 random data, 256 consecutive zeros ~never.
__global__ void k_init(const int* __restrict__ eip,
                       const float* __restrict__ w1,
                       const float* __restrict__ w2,
                       float* __restrict__ out, int out_size) {
    if (threadIdx.x != 0 || blockIdx.x != 0) return;
    int allzero = 1;
    for (int j = 0; j < 256; ++j)
        if (eip[2 * j + 1] != 0) allzero = 0;
    g_is64 = allzero;

    const int write_tail = (out_size >= H_ELEMS + 2 * OUT_CH * IN_CH);
    for (int o = 0; o < OUT_CH; ++o) {
        float m = -1e30f;
        for (int k = 0; k < IN_CH; ++k) m = fmaxf(m, w1[o * IN_CH + k]);
        float e[IN_CH], s = 0.f;
        for (int k = 0; k < IN_CH; ++k) { e[k] = expf(w1[o * IN_CH + k] - m); s += e[k]; }
        for (int k = 0; k < IN_CH; ++k) {
            float ws = e[k] / s;
            g_w1s[o * IN_CH + k] = ws;
            if (write_tail) out[H_ELEMS + o * IN_CH + k] = ws;
        }
    }
    for (int o = 0; o < OUT_CH; ++o) {
        float m = -1e30f;
        for (int k = 0; k < IN_CH; ++k) m = fmaxf(m, w2[o * IN_CH + k]);
        float e[IN_CH], s = 0.f;
        for (int k = 0; k < IN_CH; ++k) { e[k] = expf(w2[o * IN_CH + k] - m); s += e[k]; }
        for (int k = 0; k < IN_CH; ++k) {
            float ws = e[k] / s;
            g_w2s[o * IN_CH + k] = ws;
            if (write_tail) out[H_ELEMS + OUT_CH * IN_CH + o * IN_CH + k] = ws;
        }
    }
}

// Zero A2 scratch (64 MB) and row counters — every launch (graph replay).
__global__ void k_zero() {
    size_t i = (size_t)blockIdx.x * blockDim.x + threadIdx.x;
    const size_t n4 = (size_t)NN_ELEMS / 4;  // 4,194,304 uint4
    uint4 z = make_uint4(0u, 0u, 0u, 0u);
    uint4* p = (uint4*)&g_A2h[0];
    for (size_t j = i; j < n4; j += (size_t)gridDim.x * blockDim.x) p[j] = z;
    if (i <= N_NODES) g_rowcnt[i] = 0;
}

// Pass A: scatter-add A2 (both channels packed in one half2 atomic, x1024)
// + histogram rows for CSR. Reads edge_index raw (int32 or int64).
__global__ void k_scatterA(const void* __restrict__ ei,
                           const float* __restrict__ ev) {
    int i = blockIdx.x * blockDim.x + threadIdx.x;
    if (i >= KE) return;
    int k = i >> 17;           // i / EDGES
    int e = i & (EDGES - 1);   // i % EDGES
    int r, c;
    if (g_is64) {
        r = (int)((const long long*)ei)[(k * 2) * EDGES + e];
        c = (int)((const long long*)ei)[(k * 2 + 1) * EDGES + e];
    } else {
        r = ((const int*)ei)[(k * 2) * EDGES + e];
        c = ((const int*)ei)[(k * 2 + 1) * EDGES + e];
    }
    float v = ev[i];
    __half2 hv = __floats2half2_rn(g_w2s[k] * v * A2_SCALE,
                                   g_w2s[IN_CH + k] * v * A2_SCALE);
    atomicAdd(&g_A2h[(size_t)r * N_NODES + c], hv);
    atomicAdd(&g_rowcnt[r], 1);
}

// Exclusive prefix sum over 4096 row counts (single block).
__global__ void k_prefix() {
    __shared__ int ssum[1024];
    int t = threadIdx.x;
    int c0 = g_rowcnt[t * 4 + 0];
    int c1 = g_rowcnt[t * 4 + 1];
    int c2 = g_rowcnt[t * 4 + 2];
    int c3 = g_rowcnt[t * 4 + 3];
    ssum[t] = c0 + c1 + c2 + c3;
    __syncthreads();
    if (t == 0) {
        int acc = 0;
        for (int j = 0; j < 1024; ++j) { int x = ssum[j]; ssum[j] = acc; acc += x; }
    }
    __syncthreads();
    int base = ssum[t];
    int p0 = base, p1 = base + c0, p2 = p1 + c1, p3 = p2 + c2;
    g_rowptr[t * 4 + 0] = p0;  g_rowfill[t * 4 + 0] = p0;
    g_rowptr[t * 4 + 1] = p1;  g_rowfill[t * 4 + 1] = p1;
    g_rowptr[t * 4 + 2] = p2;  g_rowfill[t * 4 + 2] = p2;
    g_rowptr[t * 4 + 3] = p3;  g_rowfill[t * 4 + 3] = p3;
    if (t == 1023) g_rowptr[4096] = p3 + c3;
}

// Pass B: fill CSR columns + per-channel A1 values.
__global__ void k_scatterB(const void* __restrict__ ei,
                           const float* __restrict__ ev) {
    int i = blockIdx.x * blockDim.x + threadIdx.x;
    if (i >= KE) return;
    int k = i >> 17;
    int e = i & (EDGES - 1);
    int r, c;
    if (g_is64) {
        r = (int)((const long long*)ei)[(k * 2) * EDGES + e];
        c = (int)((const long long*)ei)[(k * 2 + 1) * EDGES + e];
    } else {
        r = ((const int*)ei)[(k * 2) * EDGES + e];
        c = ((const int*)ei)[(k * 2 + 1) * EDGES + e];
    }
    float v = ev[i];
    int pos = atomicAdd(&g_rowfill[r], 1);
    g_cols[pos] = c;
    g_v01[pos] = make_float2(g_w1s[k] * v, g_w1s[IN_CH + k] * v);
}

// SpMM: one block per A1 row, computing BOTH output channels.
// H[0,row,:] = sum_j v0_j * A2[0][c_j,:]; H[1,row,:] = sum_j v1_j * A2[1][c_j,:].
// A2 rows are half2-interleaved (ch0, ch1): one 16 KB row read serves both.
// 256 threads, each owns 4 uint4 (16 columns x both channels).
__global__ void __launch_bounds__(256) k_spmm(float* __restrict__ out) {
    const int row = blockIdx.x;
    const int tid = threadIdx.x;

    const int start = g_rowptr[row];
    const int end   = g_rowptr[row + 1];

    __shared__ int    s_col[256];
    __shared__ float2 s_v[256];

    float acc0[16], acc1[16];
    #pragma unroll
    for (int i = 0; i < 16; ++i) { acc0[i] = 0.f; acc1[i] = 0.f; }

    const uint4* __restrict__ A2u = (const uint4*)&g_A2h[0];

    for (int base = start; base < end; base += 256) {
        int n = min(256, end - base);
        if (tid < n) {
            s_col[tid] = g_cols[base + tid];
            s_v[tid]   = g_v01[base + tid];
        }
        __syncthreads();
        #pragma unroll 2
        for (int j = 0; j < n; ++j) {
            const int   c  = s_col[j];
            const float v0 = s_v[j].x;
            const float v1 = s_v[j].y;
            const uint4* r4 = A2u + (size_t)c * 1024 + tid;
            #pragma unroll
            for (int g = 0; g < 4; ++g) {
                uint4 q = __ldcg(r4 + g * 256);
                float2 f0 = __half22float2(*(const __half2*)&q.x);
                float2 f1 = __half22float2(*(const __half2*)&q.y);
                float2 f2 = __half22float2(*(const __half2*)&q.z);
                float2 f3 = __half22float2(*(const __half2*)&q.w);
                acc0[g * 4 + 0] = fmaf(v0, f0.x, acc0[g * 4 + 0]);
                acc1[g * 4 + 0] = fmaf(v1, f0.y, acc1[g * 4 + 0]);
                acc0[g * 4 + 1] = fmaf(v0, f1.x, acc0[g * 4 + 1]);
                acc1[g * 4 + 1] = fmaf(v1, f1.y, acc1[g * 4 + 1]);
                acc0[g * 4 + 2] = fmaf(v0, f2.x, acc0[g * 4 + 2]);
                acc1[g * 4 + 2] = fmaf(v1, f2.y, acc1[g * 4 + 2]);
                acc0[g * 4 + 3] = fmaf(v0, f3.x, acc0[g * 4 + 3]);
                acc1[g * 4 + 3] = fmaf(v1, f3.y, acc1[g * 4 + 3]);
            }
        }
        __syncthreads();
    }

    // Descale (exact power of 2) and stream out both H rows.
    float4* H0 = (float4*)(out + (size_t)row * N_NODES);
    float4* H1 = (float4*)(out + ((size_t)N_NODES + row) * N_NODES);
    #pragma unroll
    for (int g = 0; g < 4; ++g) {
        float4 o0 = make_float4(acc0[g * 4 + 0] * A2_DESCALE,
                                acc0[g * 4 + 1] * A2_DESCALE,
                                acc0[g * 4 + 2] * A2_DESCALE,
                                acc0[g * 4 + 3] * A2_DESCALE);
        float4 o1 = make_float4(acc1[g * 4 + 0] * A2_DESCALE,
                                acc1[g * 4 + 1] * A2_DESCALE,
                                acc1[g * 4 + 2] * A2_DESCALE,
                                acc1[g * 4 + 3] * A2_DESCALE);
        __stcs(H0 + g * 256 + tid, o0);   // streaming: don't pollute L2
        __stcs(H1 + g * 256 + tid, o1);
    }
}

// ---------------- launch ----------------
extern "C" void kernel_launch(void* const* d_in, const int* in_sizes, int n_in,
                              void* d_out, int out_size) {
    (void)in_sizes; (void)n_in;
    const void*  ei = d_in[0];                 // edge_index [5,2,E] int32 or int64
    const float* ev = (const float*)d_in[1];   // edge_value [5,E] fp32
    const float* w1 = (const float*)d_in[2];   // [2,5]
    const float* w2 = (const float*)d_in[3];   // [2,5]
    float* out = (float*)d_out;                // H [2,4096,4096] (++ W1 ++ W2)

    k_init<<<1, 32>>>((const int*)ei, w1, w2, out, out_size);      // launch 0
    k_zero<<<8192, 512>>>();                                       // launch 1
    k_scatterA<<<(KE + 511) / 512, 512>>>(ei, ev);                 // launch 2
    k_prefix<<<1, 1024>>>();                                       // launch 3
    k_scatterB<<<(KE + 511) / 512, 512>>>(ei, ev);                 // launch 4
    k_spmm<<<N_NODES, 256>>>(out);                                 // launch 5  (ncu -s 5)
}